// round 10
// baseline (speedup 1.0000x reference)
#include <cuda_runtime.h>
#include <math.h>

#define BB   8
#define NN   4096
#define TPB  256
#define QPT  4                     // queries per thread
#define QPB  (TPB * QPT)           // 1024 queries per block
#define NQCH (NN / QPB)            // 4 query chunks
#define NTCH 8                     // target chunks
#define TGT  (NN / NTCH)           // 512 targets per block
#define TILE_P (TGT / 2)           // 256 packed target-pairs (8 KB smem)
#define NRED_BLK 64
#define QTOT (2 * BB * NN)         // 65536 query slots

typedef unsigned long long ull;

// Scratch (__device__ globals; allocation forbidden)
// per-(dir,b,tchunk,query) partial mins WITH h_q already folded in.
__device__ float g_pmin[2 * BB * NTCH * NN];     // 2 MB
__device__ float g_partials[NRED_BLK];
__device__ unsigned int g_done = 0;

// ---- packed f32x2 helpers (sm_103a) --------------------------------------
__device__ __forceinline__ ull fma2(ull a, ull b, ull c) {
    ull d;
    asm("fma.rn.f32x2 %0, %1, %2, %3;" : "=l"(d) : "l"(a), "l"(b), "l"(c));
    return d;
}
__device__ __forceinline__ ull pack2(float lo, float hi) {
    ull r;
    asm("mov.b64 %0, {%1, %2};" : "=l"(r) : "f"(lo), "f"(hi));
    return r;
}
__device__ __forceinline__ void unpack2(ull v, float& lo, float& hi) {
    asm("mov.b64 {%0, %1}, %2;" : "=f"(lo), "=f"(hi) : "l"(v));
}

// Compute both relative transforms for batch b into sR/sT (called by 16 thr)
__device__ __forceinline__ void rel_transform_16(
    int tid,
    const float* __restrict__ pred_rot,   const float* __restrict__ pred_trans,
    const float* __restrict__ ctx_hyp_rot,const float* __restrict__ ctx_hyp_trans,
    const float* __restrict__ gt_rot,     const float* __restrict__ gt_trans,
    const float* __restrict__ ctx_gt_rot, const float* __restrict__ ctx_gt_trans,
    float sR[2][BB][9], float sT[2][BB][3])
{
    const int w = tid / BB, b = tid % BB;
    const float* Ra = (w == 0 ? pred_rot      : gt_rot)       + b * 9;
    const float* ta = (w == 0 ? pred_trans    : gt_trans)     + b * 3;
    const float* Rb = (w == 0 ? ctx_hyp_rot   : ctx_gt_rot)   + b * 9;
    const float* tb = (w == 0 ? ctx_hyp_trans : ctx_gt_trans) + b * 3;
    #pragma unroll
    for (int i = 0; i < 3; i++)
        #pragma unroll
        for (int k = 0; k < 3; k++) {
            float s = 0.f;
            #pragma unroll
            for (int j = 0; j < 3; j++) s += Ra[i*3+j] * Rb[k*3+j];
            sR[w][b][i*3+k] = s;
        }
    #pragma unroll
    for (int i = 0; i < 3; i++) {
        float s = ta[i];
        #pragma unroll
        for (int j = 0; j < 3; j++) s -= sR[w][b][i*3+j] * tb[j];
        sT[w][b][i] = s;
    }
}

// ---------------------------------------------------------------------------
// Kernel 1: self-transforming chamfer. grid (NQCH=4, BB, 2*NTCH=16) = 512
// blocks, 256 thr, QPT=4, launch_bounds(256,4) (proven R9 config). Each block
// recomputes the relative transforms, transforms its 512 raw targets into the
// packed smem tile and its 4 raw queries into registers, sweeps the tile, and
// stores per-(query,tchunk) mins (h_q folded) with plain coalesced stores.
// No prep kernel, no atomics, no init pass.
// ---------------------------------------------------------------------------
__global__ void __launch_bounds__(TPB, 4) k_chamfer(
    const float* __restrict__ pred_rot,   const float* __restrict__ pred_trans,
    const float* __restrict__ ctx_hyp_rot,const float* __restrict__ ctx_hyp_trans,
    const float* __restrict__ gt_rot,     const float* __restrict__ gt_trans,
    const float* __restrict__ ctx_gt_rot, const float* __restrict__ ctx_gt_trans,
    const float* __restrict__ mp)
{
    __shared__ float4 s_xy[TILE_P];
    __shared__ float4 s_zh[TILE_P];
    __shared__ float  s_raw[TGT * 3];          // 6 KB raw target staging
    __shared__ float  sR[2][BB][9];
    __shared__ float  sT[2][BB][3];

    const int dir = blockIdx.z >> 3;
    const int tc  = blockIdx.z & 7;
    const int b   = blockIdx.y;
    const int tid = threadIdx.x;

    if (tid < 2 * BB)
        rel_transform_16(tid, pred_rot, pred_trans, ctx_hyp_rot, ctx_hyp_trans,
                         gt_rot, gt_trans, ctx_gt_rot, ctx_gt_trans, sR, sT);

    // coalesced staging of this block's 512 raw target points (1536 floats)
    {
        const float* src = mp + (b * NN + tc * TGT) * 3;
        #pragma unroll
        for (int i = tid; i < TGT * 3; i += TPB) s_raw[i] = src[i];
    }
    __syncthreads();

    // transform 2 targets per thread into packed tile (w = 1-dir)
    {
        const float* R = sR[1 - dir][b];
        const float* t = sT[1 - dir][b];
        const int p = tid;                      // packed pair index
        float xx[2], yy[2], zz[2], hh[2];
        #pragma unroll
        for (int l = 0; l < 2; l++) {
            const float px = s_raw[(2*p + l)*3 + 0];
            const float py = s_raw[(2*p + l)*3 + 1];
            const float pz = s_raw[(2*p + l)*3 + 2];
            float x = fmaf(R[0], px, fmaf(R[1], py, fmaf(R[2], pz, t[0])));
            float y = fmaf(R[3], px, fmaf(R[4], py, fmaf(R[5], pz, t[1])));
            float z = fmaf(R[6], px, fmaf(R[7], py, fmaf(R[8], pz, t[2])));
            xx[l] = x; yy[l] = y; zz[l] = z;
            hh[l] = 0.5f * fmaf(x, x, fmaf(y, y, z * z));
        }
        s_xy[p] = make_float4(xx[0], xx[1], yy[0], yy[1]);
        s_zh[p] = make_float4(zz[0], zz[1], hh[0], hh[1]);
    }

    // transform 4 queries per thread (w = dir), keep packed-negated + h
    const int nbase = blockIdx.x * QPB + tid;
    ull nx[QPT], ny[QPT], nz[QPT];
    float hq[QPT];
    {
        const float* R = sR[dir][b];
        const float* t = sT[dir][b];
        #pragma unroll
        for (int k = 0; k < QPT; k++) {
            const float* p = mp + (b * NN + nbase + k * TPB) * 3;
            const float px = p[0], py = p[1], pz = p[2];
            float x = fmaf(R[0], px, fmaf(R[1], py, fmaf(R[2], pz, t[0])));
            float y = fmaf(R[3], px, fmaf(R[4], py, fmaf(R[5], pz, t[1])));
            float z = fmaf(R[6], px, fmaf(R[7], py, fmaf(R[8], pz, t[2])));
            hq[k] = 0.5f * fmaf(x, x, fmaf(y, y, z * z));
            nx[k] = pack2(-x, -x);
            ny[k] = pack2(-y, -y);
            nz[k] = pack2(-z, -z);
        }
    }

    float ma[QPT], mb[QPT];
    #pragma unroll
    for (int k = 0; k < QPT; k++) { ma[k] = INFINITY; mb[k] = INFINITY; }

    __syncthreads();

    const ulonglong2* __restrict__ axy = (const ulonglong2*)s_xy;
    const ulonglong2* __restrict__ azh = (const ulonglong2*)s_zh;

    #pragma unroll 4
    for (int j = 0; j < TILE_P; j++) {
        const ulonglong2 A = axy[j];   // (x0,x1) (y0,y1)
        const ulonglong2 B = azh[j];   // (z0,z1) (h0,h1)
        #pragma unroll
        for (int k = 0; k < QPT; k++) {
            ull v = fma2(nz[k], B.x, B.y);
            v = fma2(ny[k], A.y, v);
            v = fma2(nx[k], A.x, v);
            float lo, hi;
            unpack2(v, lo, hi);
            ma[k] = fminf(ma[k], lo);
            mb[k] = fminf(mb[k], hi);
        }
    }

    // store per-(query, tchunk) partial min with h_q folded; coalesced
    {
        const int db = dir * BB + b;
        float* __restrict__ dst = &g_pmin[(db * NTCH + tc) * NN];
        #pragma unroll
        for (int k = 0; k < QPT; k++)
            dst[nbase + k * TPB] = fminf(ma[k], mb[k]) + hq[k];
    }
}

// ---------------------------------------------------------------------------
// Deterministic block sum reduction (valid in thread 0)
// ---------------------------------------------------------------------------
__device__ __forceinline__ float block_reduce_sum(float v)
{
    __shared__ float ws[TPB / 32];
    #pragma unroll
    for (int o = 16; o > 0; o >>= 1) v += __shfl_down_sync(0xffffffffu, v, o);
    if ((threadIdx.x & 31) == 0) ws[threadIdx.x >> 5] = v;
    __syncthreads();
    if (threadIdx.x < 32) {
        v = (threadIdx.x < TPB / 32) ? ws[threadIdx.x] : 0.f;
        #pragma unroll
        for (int o = 4; o > 0; o >>= 1) v += __shfl_down_sync(0xffffffffu, v, o);
    }
    return v;
}

// ---------------------------------------------------------------------------
// Kernel 2: min over 8 tchunks per query, deferred sqrt, global sum.
// Last finished block also computes loss_trans from the raw inputs.
// ---------------------------------------------------------------------------
__global__ void __launch_bounds__(TPB) k_reduce(
    const float* __restrict__ pred_rot,   const float* __restrict__ pred_trans,
    const float* __restrict__ ctx_hyp_rot,const float* __restrict__ ctx_hyp_trans,
    const float* __restrict__ gt_rot,     const float* __restrict__ gt_trans,
    const float* __restrict__ ctx_gt_rot, const float* __restrict__ ctx_gt_trans,
    float* __restrict__ out)
{
    const int tid = threadIdx.x;

    float s = 0.f;
    #pragma unroll
    for (int k = 0; k < 4; k++) {
        const int q  = blockIdx.x * (QTOT / NRED_BLK) + tid + k * TPB;
        const int db = q >> 12;          // (dir*BB + b)
        const int ql = q & (NN - 1);
        float m = INFINITY;
        #pragma unroll
        for (int tc = 0; tc < NTCH; tc++)
            m = fminf(m, g_pmin[(db * NTCH + tc) * NN + ql]);
        s += sqrtf(fmaxf(2.0f * m, 0.0f));
    }

    float bs = block_reduce_sum(s);

    __shared__ bool is_last;
    if (tid == 0) {
        g_partials[blockIdx.x] = bs;
        __threadfence();
        is_last = (atomicAdd(&g_done, 1u) == NRED_BLK - 1);
    }
    __syncthreads();

    if (is_last) {
        const volatile float* vp = g_partials;
        float v = (tid < NRED_BLK) ? vp[tid] : 0.f;
        float tot = block_reduce_sum(v);
        if (tid == 0) {
            out[0] = tot * (1.0f / (BB * NN));
            // loss_trans from raw inputs (tiny)
            float lt = 0.f;
            for (int w = 0; w < 2; w++)
                for (int b = 0; b < BB; b++) {
                    const float* Ra = (w == 0 ? pred_rot      : gt_rot)       + b * 9;
                    const float* ta = (w == 0 ? pred_trans    : gt_trans)     + b * 3;
                    const float* Rb = (w == 0 ? ctx_hyp_rot   : ctx_gt_rot)   + b * 9;
                    const float* tb = (w == 0 ? ctx_hyp_trans : ctx_gt_trans) + b * 3;
                    float tr[3];
                    for (int i = 0; i < 3; i++) {
                        float acc = ta[i];
                        for (int j = 0; j < 3; j++) {
                            float r = 0.f;
                            for (int kk = 0; kk < 3; kk++) r += Ra[i*3+kk] * Rb[j*3+kk];
                            acc -= r * tb[j];
                        }
                        tr[i] = acc;
                    }
                    if (w == 0) { out[2] = 0.f; }  // no-op keep regs simple
                    // accumulate |pred - gt| lazily: store pred in out? do directly:
                    // recompute both inside one pass instead:
                    (void)tr;
                }
            // direct two-pass recompute for clarity/correctness:
            lt = 0.f;
            for (int b = 0; b < BB; b++) {
                float trp[3], trg[3];
                for (int w = 0; w < 2; w++) {
                    const float* Ra = (w == 0 ? pred_rot      : gt_rot)       + b * 9;
                    const float* ta = (w == 0 ? pred_trans    : gt_trans)     + b * 3;
                    const float* Rb = (w == 0 ? ctx_hyp_rot   : ctx_gt_rot)   + b * 9;
                    const float* tb = (w == 0 ? ctx_hyp_trans : ctx_gt_trans) + b * 3;
                    float* tr = (w == 0 ? trp : trg);
                    for (int i = 0; i < 3; i++) {
                        float acc = ta[i];
                        for (int j = 0; j < 3; j++) {
                            float r = 0.f;
                            for (int kk = 0; kk < 3; kk++) r += Ra[i*3+kk] * Rb[j*3+kk];
                            acc -= r * tb[j];
                        }
                        tr[i] = acc;
                    }
                }
                for (int i = 0; i < 3; i++) lt += fabsf(trp[i] - trg[i]);
            }
            out[1] = lt * (1.0f / (BB * 3));
            g_done = 0;   // reset for next graph replay
        }
    }
}

// ---------------------------------------------------------------------------
extern "C" void kernel_launch(void* const* d_in, const int* in_sizes, int n_in,
                              void* d_out, int out_size)
{
    const float* pred_rot      = (const float*)d_in[0];
    const float* pred_trans    = (const float*)d_in[1];
    const float* ctx_hyp_rot   = (const float*)d_in[2];
    const float* ctx_hyp_trans = (const float*)d_in[3];
    const float* gt_rot        = (const float*)d_in[4];
    const float* gt_trans      = (const float*)d_in[5];
    const float* ctx_gt_rot    = (const float*)d_in[6];
    const float* ctx_gt_trans  = (const float*)d_in[7];
    const float* model_points  = (const float*)d_in[8];
    float* out = (float*)d_out;

    k_chamfer<<<dim3(NQCH, BB, 2 * NTCH), TPB>>>(
        pred_rot, pred_trans, ctx_hyp_rot, ctx_hyp_trans,
        gt_rot, gt_trans, ctx_gt_rot, ctx_gt_trans, model_points);
    k_reduce<<<NRED_BLK, TPB>>>(
        pred_rot, pred_trans, ctx_hyp_rot, ctx_hyp_trans,
        gt_rot, gt_trans, ctx_gt_rot, ctx_gt_trans, out);
}

// round 11
// speedup vs baseline: 1.0982x; 1.0982x over previous
#include <cuda_runtime.h>
#include <math.h>

#define BB   8
#define NN   4096
#define TPB  256
#define QPT  4                     // queries per thread
#define QPB  (TPB * QPT)           // 1024 queries per block
#define NQCH (NN / QPB)            // 4 query chunks
#define NTCH 8                     // target chunks
#define TGT  (NN / NTCH)           // 512 targets per block
#define TILE_P (TGT / 2)           // 256 packed target-pairs (8 KB smem)
#define NRED_BLK 256
#define QTOT (2 * BB * NN)         // 65536 query slots

typedef unsigned long long ull;

// Scratch (__device__ globals; allocation forbidden)
// per-(dir,b,tchunk,query) partial mins WITH h_q already folded in.
__device__ float g_pmin[2 * BB * NTCH * NN];     // 2 MB
__device__ float g_partials[NRED_BLK];
__device__ unsigned int g_done = 0;

// ---- packed f32x2 helpers (sm_103a) --------------------------------------
__device__ __forceinline__ ull fma2(ull a, ull b, ull c) {
    ull d;
    asm("fma.rn.f32x2 %0, %1, %2, %3;" : "=l"(d) : "l"(a), "l"(b), "l"(c));
    return d;
}
__device__ __forceinline__ ull pack2(float lo, float hi) {
    ull r;
    asm("mov.b64 %0, {%1, %2};" : "=l"(r) : "f"(lo), "f"(hi));
    return r;
}
__device__ __forceinline__ void unpack2(ull v, float& lo, float& hi) {
    asm("mov.b64 {%0, %1}, %2;" : "=f"(lo), "=f"(hi) : "l"(v));
}

// Compute both relative transforms for batch b into sR/sT (called by 16 thr)
__device__ __forceinline__ void rel_transform_16(
    int tid,
    const float* __restrict__ pred_rot,   const float* __restrict__ pred_trans,
    const float* __restrict__ ctx_hyp_rot,const float* __restrict__ ctx_hyp_trans,
    const float* __restrict__ gt_rot,     const float* __restrict__ gt_trans,
    const float* __restrict__ ctx_gt_rot, const float* __restrict__ ctx_gt_trans,
    float sR[2][BB][9], float sT[2][BB][3])
{
    const int w = tid / BB, b = tid % BB;
    const float* Ra = (w == 0 ? pred_rot      : gt_rot)       + b * 9;
    const float* ta = (w == 0 ? pred_trans    : gt_trans)     + b * 3;
    const float* Rb = (w == 0 ? ctx_hyp_rot   : ctx_gt_rot)   + b * 9;
    const float* tb = (w == 0 ? ctx_hyp_trans : ctx_gt_trans) + b * 3;
    #pragma unroll
    for (int i = 0; i < 3; i++)
        #pragma unroll
        for (int k = 0; k < 3; k++) {
            float s = 0.f;
            #pragma unroll
            for (int j = 0; j < 3; j++) s += Ra[i*3+j] * Rb[k*3+j];
            sR[w][b][i*3+k] = s;
        }
    #pragma unroll
    for (int i = 0; i < 3; i++) {
        float s = ta[i];
        #pragma unroll
        for (int j = 0; j < 3; j++) s -= sR[w][b][i*3+j] * tb[j];
        sT[w][b][i] = s;
    }
}

// ---------------------------------------------------------------------------
// Kernel 1: self-transforming chamfer (unchanged from R10 — proven).
// grid (NQCH=4, BB, 2*NTCH=16) = 512 blocks, 256 thr, QPT=4, lb(256,4).
// ---------------------------------------------------------------------------
__global__ void __launch_bounds__(TPB, 4) k_chamfer(
    const float* __restrict__ pred_rot,   const float* __restrict__ pred_trans,
    const float* __restrict__ ctx_hyp_rot,const float* __restrict__ ctx_hyp_trans,
    const float* __restrict__ gt_rot,     const float* __restrict__ gt_trans,
    const float* __restrict__ ctx_gt_rot, const float* __restrict__ ctx_gt_trans,
    const float* __restrict__ mp)
{
    __shared__ float4 s_xy[TILE_P];
    __shared__ float4 s_zh[TILE_P];
    __shared__ float  s_raw[TGT * 3];          // 6 KB raw target staging
    __shared__ float  sR[2][BB][9];
    __shared__ float  sT[2][BB][3];

    const int dir = blockIdx.z >> 3;
    const int tc  = blockIdx.z & 7;
    const int b   = blockIdx.y;
    const int tid = threadIdx.x;

    if (tid < 2 * BB)
        rel_transform_16(tid, pred_rot, pred_trans, ctx_hyp_rot, ctx_hyp_trans,
                         gt_rot, gt_trans, ctx_gt_rot, ctx_gt_trans, sR, sT);

    // coalesced staging of this block's 512 raw target points (1536 floats)
    {
        const float* src = mp + (b * NN + tc * TGT) * 3;
        #pragma unroll
        for (int i = tid; i < TGT * 3; i += TPB) s_raw[i] = src[i];
    }
    __syncthreads();

    // transform 2 targets per thread into packed tile (w = 1-dir)
    {
        const float* R = sR[1 - dir][b];
        const float* t = sT[1 - dir][b];
        const int p = tid;                      // packed pair index
        float xx[2], yy[2], zz[2], hh[2];
        #pragma unroll
        for (int l = 0; l < 2; l++) {
            const float px = s_raw[(2*p + l)*3 + 0];
            const float py = s_raw[(2*p + l)*3 + 1];
            const float pz = s_raw[(2*p + l)*3 + 2];
            float x = fmaf(R[0], px, fmaf(R[1], py, fmaf(R[2], pz, t[0])));
            float y = fmaf(R[3], px, fmaf(R[4], py, fmaf(R[5], pz, t[1])));
            float z = fmaf(R[6], px, fmaf(R[7], py, fmaf(R[8], pz, t[2])));
            xx[l] = x; yy[l] = y; zz[l] = z;
            hh[l] = 0.5f * fmaf(x, x, fmaf(y, y, z * z));
        }
        s_xy[p] = make_float4(xx[0], xx[1], yy[0], yy[1]);
        s_zh[p] = make_float4(zz[0], zz[1], hh[0], hh[1]);
    }

    // transform 4 queries per thread (w = dir), keep packed-negated + h
    const int nbase = blockIdx.x * QPB + tid;
    ull nx[QPT], ny[QPT], nz[QPT];
    float hq[QPT];
    {
        const float* R = sR[dir][b];
        const float* t = sT[dir][b];
        #pragma unroll
        for (int k = 0; k < QPT; k++) {
            const float* p = mp + (b * NN + nbase + k * TPB) * 3;
            const float px = p[0], py = p[1], pz = p[2];
            float x = fmaf(R[0], px, fmaf(R[1], py, fmaf(R[2], pz, t[0])));
            float y = fmaf(R[3], px, fmaf(R[4], py, fmaf(R[5], pz, t[1])));
            float z = fmaf(R[6], px, fmaf(R[7], py, fmaf(R[8], pz, t[2])));
            hq[k] = 0.5f * fmaf(x, x, fmaf(y, y, z * z));
            nx[k] = pack2(-x, -x);
            ny[k] = pack2(-y, -y);
            nz[k] = pack2(-z, -z);
        }
    }

    float ma[QPT], mb[QPT];
    #pragma unroll
    for (int k = 0; k < QPT; k++) { ma[k] = INFINITY; mb[k] = INFINITY; }

    __syncthreads();

    const ulonglong2* __restrict__ axy = (const ulonglong2*)s_xy;
    const ulonglong2* __restrict__ azh = (const ulonglong2*)s_zh;

    #pragma unroll 4
    for (int j = 0; j < TILE_P; j++) {
        const ulonglong2 A = axy[j];   // (x0,x1) (y0,y1)
        const ulonglong2 B = azh[j];   // (z0,z1) (h0,h1)
        #pragma unroll
        for (int k = 0; k < QPT; k++) {
            ull v = fma2(nz[k], B.x, B.y);
            v = fma2(ny[k], A.y, v);
            v = fma2(nx[k], A.x, v);
            float lo, hi;
            unpack2(v, lo, hi);
            ma[k] = fminf(ma[k], lo);
            mb[k] = fminf(mb[k], hi);
        }
    }

    // store per-(query, tchunk) partial min with h_q folded; coalesced
    {
        const int db = dir * BB + b;
        float* __restrict__ dst = &g_pmin[(db * NTCH + tc) * NN];
        #pragma unroll
        for (int k = 0; k < QPT; k++)
            dst[nbase + k * TPB] = fminf(ma[k], mb[k]) + hq[k];
    }
}

// ---------------------------------------------------------------------------
// Deterministic block sum reduction (valid in thread 0)
// ---------------------------------------------------------------------------
__device__ __forceinline__ float block_reduce_sum(float v)
{
    __shared__ float ws[TPB / 32];
    #pragma unroll
    for (int o = 16; o > 0; o >>= 1) v += __shfl_down_sync(0xffffffffu, v, o);
    if ((threadIdx.x & 31) == 0) ws[threadIdx.x >> 5] = v;
    __syncthreads();
    if (threadIdx.x < 32) {
        v = (threadIdx.x < TPB / 32) ? ws[threadIdx.x] : 0.f;
        #pragma unroll
        for (int o = 4; o > 0; o >>= 1) v += __shfl_down_sync(0xffffffffu, v, o);
    }
    return v;
}

// ---------------------------------------------------------------------------
// Kernel 2: reduce. 256 blocks x 256 thr, 1 query/thread: min over 8 tchunks
// (8 independent coalesced L2 loads, MLP=8), deferred sqrt, block sum.
// Block 0 computes loss_trans IN PARALLEL (16-thread rel transforms -> smem).
// Last finished block does the fixed-order final sum of 256 partials.
// ---------------------------------------------------------------------------
__global__ void __launch_bounds__(TPB) k_reduce(
    const float* __restrict__ pred_rot,   const float* __restrict__ pred_trans,
    const float* __restrict__ ctx_hyp_rot,const float* __restrict__ ctx_hyp_trans,
    const float* __restrict__ gt_rot,     const float* __restrict__ gt_trans,
    const float* __restrict__ ctx_gt_rot, const float* __restrict__ ctx_gt_trans,
    float* __restrict__ out)
{
    const int tid = threadIdx.x;

    // block 0: parallel loss_trans
    __shared__ float sR[2][BB][9];
    __shared__ float sT[2][BB][3];
    if (blockIdx.x == 0) {
        if (tid < 2 * BB)
            rel_transform_16(tid, pred_rot, pred_trans, ctx_hyp_rot, ctx_hyp_trans,
                             gt_rot, gt_trans, ctx_gt_rot, ctx_gt_trans, sR, sT);
        __syncthreads();
        if (tid == 0) {
            float lt = 0.f;
            #pragma unroll
            for (int b = 0; b < BB; b++)
                #pragma unroll
                for (int i = 0; i < 3; i++)
                    lt += fabsf(sT[0][b][i] - sT[1][b][i]);
            out[1] = lt * (1.0f / (BB * 3));
        }
    }

    // 1 query per thread: min over the 8 tchunk partials (h_q folded in)
    const int q  = blockIdx.x * TPB + tid;   // < QTOT
    const int db = q >> 12;                  // dir*BB + b
    const int ql = q & (NN - 1);
    float m = INFINITY;
    #pragma unroll
    for (int tc = 0; tc < NTCH; tc++)
        m = fminf(m, g_pmin[(db * NTCH + tc) * NN + ql]);
    float s = sqrtf(fmaxf(2.0f * m, 0.0f));

    float bs = block_reduce_sum(s);

    __shared__ bool is_last;
    if (tid == 0) {
        g_partials[blockIdx.x] = bs;
        __threadfence();
        is_last = (atomicAdd(&g_done, 1u) == NRED_BLK - 1);
    }
    __syncthreads();

    if (is_last) {
        const volatile float* vp = g_partials;
        float v = vp[tid];                    // exactly NRED_BLK == TPB
        float tot = block_reduce_sum(v);
        if (tid == 0) {
            out[0] = tot * (1.0f / (BB * NN));
            g_done = 0;   // reset for next graph replay
        }
    }
}

// ---------------------------------------------------------------------------
extern "C" void kernel_launch(void* const* d_in, const int* in_sizes, int n_in,
                              void* d_out, int out_size)
{
    const float* pred_rot      = (const float*)d_in[0];
    const float* pred_trans    = (const float*)d_in[1];
    const float* ctx_hyp_rot   = (const float*)d_in[2];
    const float* ctx_hyp_trans = (const float*)d_in[3];
    const float* gt_rot        = (const float*)d_in[4];
    const float* gt_trans      = (const float*)d_in[5];
    const float* ctx_gt_rot    = (const float*)d_in[6];
    const float* ctx_gt_trans  = (const float*)d_in[7];
    const float* model_points  = (const float*)d_in[8];
    float* out = (float*)d_out;

    k_chamfer<<<dim3(NQCH, BB, 2 * NTCH), TPB>>>(
        pred_rot, pred_trans, ctx_hyp_rot, ctx_hyp_trans,
        gt_rot, gt_trans, ctx_gt_rot, ctx_gt_trans, model_points);
    k_reduce<<<NRED_BLK, TPB>>>(
        pred_rot, pred_trans, ctx_hyp_rot, ctx_hyp_trans,
        gt_rot, gt_trans, ctx_gt_rot, ctx_gt_trans, out);
}